// round 9
// baseline (speedup 1.0000x reference)
#include <cuda_runtime.h>
#include <cstdint>

// Problem constants (B=1024, T=4096, N=2048, K=16, M=2^16)
#define T_DIM   4096
#define N_DIM   2048
#define K_DIM   16
#define B_DIM   1024
#define W_DIM   (T_DIM / 32)        // 128 bitset words per batch row

// Transposed global bitset: bitset_T[w][b] (512 KB, L2-resident).
// Column reads (fixed w, consecutive b) are fully coalesced.
__device__ unsigned bitset_T[W_DIM * B_DIM];

__global__ void pack_bits_T_kernel(const int* __restrict__ in, int B) {
    // One warp produces one bitset word: g -> (b, w)
    int g    = blockIdx.x * (blockDim.x >> 5) + (threadIdx.x >> 5);
    int lane = threadIdx.x & 31;
    if (g < B * W_DIM) {
        int b = g >> 7;             // g / 128
        int w = g & (W_DIM - 1);    // g % 128
        unsigned word = __ballot_sync(0xFFFFFFFFu,
                                      in[(size_t)b * T_DIM + w * 32 + lane] != 0);
        if (lane == 0) bitset_T[w * B_DIM + b] = word;
    }
}

__device__ __forceinline__ int ldcg_i32(const int* p) {
    int v;
    asm volatile("ld.global.cg.b32 %0, [%1];" : "=r"(v) : "l"(p));
    return v;
}

__device__ __forceinline__ void stcg_f32(float* p, float v) {
    asm volatile("st.global.cg.f32 [%0], %1;" :: "l"(p), "f"(v));
}

// Neuron-major gather: one CTA per neuron. All of this CTA's 1024 table
// lookups land in ONE 256KB slab of `memory` (1-2 pages, ~128 DRAM rows),
// clustering row activates and making the TLB footprint per SM trivial.
#define GTHREADS 512

__global__ __launch_bounds__(GTHREADS)
void ram_gather_kernel(const int* __restrict__ conn,     // [N, K]
                       const int* __restrict__ memory,   // [N, M]
                       float*     __restrict__ out,      // [B, N]
                       int B)
{
    const int n = blockIdx.x;

    __shared__ unsigned cw[K_DIM];  // word index  (c >> 5)
    __shared__ unsigned cp[K_DIM];  // bit position (c & 31)
    if (threadIdx.x < K_DIM) {
        int c = conn[n * K_DIM + threadIdx.x];
        cw[threadIdx.x] = ((unsigned)c) >> 5;
        cp[threadIdx.x] = ((unsigned)c) & 31u;
    }
    __syncthreads();

    const int* mrow = memory + ((size_t)n << 16);

    for (int b = threadIdx.x; b < B; b += GTHREADS) {
        // Build the 16-bit address: 16 coalesced, L2-hot bitset column reads
        // (index cw[k]*B + b: same column for all lanes, consecutive b).
        unsigned a = 0;
#pragma unroll
        for (int k = 0; k < K_DIM; ++k) {
            unsigned word = __ldg(&bitset_T[cw[k] * B_DIM + b]);
            a |= ((word >> cp[k]) & 1u) << k;
        }
        // Random gather confined to this neuron's 256KB slab.
        int v = ldcg_i32(mrow + a);
        // Scatter store (stride 8KB); out is L2-resident so sectors merge.
        stcg_f32(out + (size_t)b * N_DIM + n, (float)(v & 1));
    }
}

extern "C" void kernel_launch(void* const* d_in, const int* in_sizes, int n_in,
                              void* d_out, int out_size) {
    // Identify inputs by unique element counts (robust to metadata order):
    //   input_bits : B*T = 4,194,304   connections: N*K = 32,768
    //   memory     : N*M = 134,217,728
    const int* input_bits  = nullptr;
    const int* connections = nullptr;
    const int* memory      = nullptr;
    long long sz_bits = 0;

    for (int i = 0; i < n_in; ++i) {
        long long s = in_sizes[i];
        if (s == (long long)N_DIM * K_DIM) {
            connections = (const int*)d_in[i];
        } else if (s == (long long)N_DIM * 65536LL) {
            memory = (const int*)d_in[i];
        } else {
            input_bits = (const int*)d_in[i];
            sz_bits = s;
        }
    }

    // 32B L2 fetch granularity: measured to cut gather DRAM traffic 248->88MB.
    // Set only when not capturing (state persists into graph replays).
    cudaStreamCaptureStatus cap = cudaStreamCaptureStatusNone;
    cudaStreamIsCapturing((cudaStream_t)0, &cap);
    if (cap == cudaStreamCaptureStatusNone) {
        cudaDeviceSetLimit(cudaLimitMaxL2FetchGranularity, 32);
        cudaGetLastError();
    }

    const int B = (int)(sz_bits / T_DIM);   // 1024

    int words = B * W_DIM;                   // 128K warp-tasks
    int blocks = (words * 32 + 255) / 256;
    pack_bits_T_kernel<<<blocks, 256>>>(input_bits, B);

    ram_gather_kernel<<<N_DIM, GTHREADS>>>(connections, memory,
                                           (float*)d_out, B);
}

// round 10
// speedup vs baseline: 1.3839x; 1.3839x over previous
#include <cuda_runtime.h>
#include <cstdint>

// Problem constants (B=1024, T=4096, N=2048, K=16, M=2^16)
#define T_DIM   4096
#define N_DIM   2048
#define K_DIM   16
#define B_DIM   1024
#define BW_DIM  (B_DIM / 32)     // 32 b-words per bit-plane
#define GTHREADS 512

// Stage 1: row-major bitset  rowbits[b][w]  (b-th row, word w covers t=w*32..)
__device__ unsigned rowbits[B_DIM * (T_DIM / 32)];
// Stage 2: bit-plane transpose  tbit[t][bw]  (bit (b&31) of word = input[b][t])
__device__ unsigned tbit[T_DIM * BW_DIM];

__global__ void pack_rowbits_kernel(const int* __restrict__ in) {
    // one warp per batch row b; 128 ballots, fully coalesced reads
    int b    = blockIdx.x * (blockDim.x >> 5) + (threadIdx.x >> 5);
    int lane = threadIdx.x & 31;
    if (b < B_DIM) {
        const int* row = in + (size_t)b * T_DIM;
        for (int w = 0; w < T_DIM / 32; ++w) {
            unsigned word = __ballot_sync(0xFFFFFFFFu, row[w * 32 + lane] != 0);
            if (lane == 0) rowbits[b * (T_DIM / 32) + w] = word;
        }
    }
}

__global__ void bit_transpose_kernel() {
    // one warp per 32x32 bit tile: (bb, wt) -> 32 ballots
    int tile = blockIdx.x * (blockDim.x >> 5) + (threadIdx.x >> 5);
    int lane = threadIdx.x & 31;
    if (tile < BW_DIM * (T_DIM / 32)) {
        int bb = tile / (T_DIM / 32);
        int wt = tile % (T_DIM / 32);
        unsigned r = rowbits[(bb * 32 + lane) * (T_DIM / 32) + wt];
        unsigned mine = 0;
#pragma unroll
        for (int j = 0; j < 32; ++j) {
            unsigned col = __ballot_sync(0xFFFFFFFFu, (r >> j) & 1u);
            if (lane == j) mine = col;
        }
        // word for t = wt*32 + lane, b-word bb; bit i of word = input[bb*32+i][t]
        tbit[(wt * 32 + lane) * BW_DIM + bb] = mine;
    }
}

__device__ __forceinline__ int ldcg_i32(const int* p) {
    int v;
    asm volatile("ld.global.cg.b32 %0, [%1];" : "=r"(v) : "l"(p));
    return v;
}
__device__ __forceinline__ void stcg_f32(float* p, float v) {
    asm volatile("st.global.cg.f32 [%0], %1;" :: "l"(p), "f"(v));
}

// One CTA per neuron: build all B addresses, counting-sort by DRAM row
// (addr>>8 : 256 entries * 4B = 1KB), issue gathers in row-sorted order so
// same-row requests land in the same warp instruction (temporal clustering).
__global__ __launch_bounds__(GTHREADS)
void ram_gather_kernel(const int* __restrict__ conn,     // [N, K]
                       const int* __restrict__ memory,   // [N, M]
                       float*     __restrict__ out)      // [B, N]
{
    const int n    = blockIdx.x;
    const int tid  = threadIdx.x;
    const int lane = tid & 31;

    __shared__ int      sc[K_DIM];          // connection t-indices
    __shared__ unsigned cnt[256];           // row counts
    __shared__ unsigned scn[256];           // inclusive scan
    __shared__ unsigned head[256];          // placement cursors
    __shared__ unsigned short sortedA[B_DIM];
    __shared__ unsigned short sortedB[B_DIM];

    if (tid < K_DIM) sc[tid] = conn[n * K_DIM + tid];
    if (tid < 256) cnt[tid] = 0;
    __syncthreads();

    // ---- Build addresses: warp = 32 consecutive b sharing one b-word ----
    // lane k (k<16) loads the plane word tbit[c_k][bw]; shuffle-broadcast.
    unsigned myA[B_DIM / GTHREADS];   // 2 items per thread
    unsigned myB[B_DIM / GTHREADS];
#pragma unroll
    for (int j = 0; j < B_DIM / GTHREADS; ++j) {
        int b  = j * GTHREADS + tid;          // warp covers 32 consecutive b
        int bw = b >> 5;
        unsigned w16 = 0;
        if (lane < K_DIM) w16 = __ldg(&tbit[sc[lane] * BW_DIM + bw]);
        unsigned a = 0;
#pragma unroll
        for (int k = 0; k < K_DIM; ++k) {
            unsigned wk = __shfl_sync(0xFFFFFFFFu, w16, k);
            a |= ((wk >> lane) & 1u) << k;    // bit (b&31) == lane
        }
        myA[j] = a;
        myB[j] = (unsigned)b;
        atomicAdd(&cnt[a >> 8], 1u);
    }
    __syncthreads();

    // ---- Inclusive scan of 256 counts (Hillis-Steele) ----
    if (tid < 256) scn[tid] = cnt[tid];
    __syncthreads();
    for (int d = 1; d < 256; d <<= 1) {
        unsigned v = 0;
        if (tid < 256 && tid >= d) v = scn[tid - d];
        __syncthreads();
        if (tid < 256) scn[tid] += v;
        __syncthreads();
    }
    if (tid < 256) head[tid] = scn[tid] - cnt[tid];   // exclusive start
    __syncthreads();

    // ---- Place items into row-sorted order ----
#pragma unroll
    for (int j = 0; j < B_DIM / GTHREADS; ++j) {
        unsigned key = myA[j] >> 8;
        unsigned pos = atomicAdd(&head[key], 1u);
        sortedA[pos] = (unsigned short)myA[j];
        sortedB[pos] = (unsigned short)myB[j];
    }
    __syncthreads();

    // ---- Row-sorted gather: same-row requests share a warp instruction ----
    const int* mrow = memory + ((size_t)n << 16);
#pragma unroll
    for (int j = 0; j < B_DIM / GTHREADS; ++j) {
        int i = j * GTHREADS + tid;
        unsigned a = sortedA[i];
        unsigned b = sortedB[i];
        int v = ldcg_i32(mrow + a);
        stcg_f32(out + (size_t)b * N_DIM + n, (float)(v & 1));
    }
}

extern "C" void kernel_launch(void* const* d_in, const int* in_sizes, int n_in,
                              void* d_out, int out_size) {
    // Identify inputs by unique element counts (robust to metadata order)
    const int* input_bits  = nullptr;
    const int* connections = nullptr;
    const int* memory      = nullptr;

    for (int i = 0; i < n_in; ++i) {
        long long s = in_sizes[i];
        if (s == (long long)N_DIM * K_DIM)            connections = (const int*)d_in[i];
        else if (s == (long long)N_DIM * 65536LL)     memory      = (const int*)d_in[i];
        else                                          input_bits  = (const int*)d_in[i];
    }

    // 32B L2 fetch granularity (measured: gather DRAM traffic 248->88MB).
    cudaStreamCaptureStatus cap = cudaStreamCaptureStatusNone;
    cudaStreamIsCapturing((cudaStream_t)0, &cap);
    if (cap == cudaStreamCaptureStatusNone) {
        cudaDeviceSetLimit(cudaLimitMaxL2FetchGranularity, 32);
        cudaGetLastError();
    }

    // Stage 1: rowbits (one warp per b): 1024 warps / 8 per block
    pack_rowbits_kernel<<<B_DIM / 8, 256>>>(input_bits);
    // Stage 2: 32x32 bit transpose: 32*128 = 4096 warp tiles / 8 per block
    bit_transpose_kernel<<<(BW_DIM * (T_DIM / 32)) / 8, 256>>>();
    // Stage 3: row-sorted gather, one CTA per neuron
    ram_gather_kernel<<<N_DIM, GTHREADS>>>(connections, memory, (float*)d_out);
}

// round 11
// speedup vs baseline: 1.5772x; 1.1397x over previous
#include <cuda_runtime.h>
#include <cstdint>

// Problem constants (B=1024, T=4096, N=2048, K=16, M=2^16)
#define T_DIM   4096
#define N_DIM   2048
#define K_DIM   16
#define B_DIM   1024
#define BW_DIM  (B_DIM / 32)     // 32 b-words per bit-plane
#define GTHREADS 512

// Bit-plane transposed input: tbit[t][bw], bit (b&31) = input[b][t]. 512 KB.
__device__ unsigned tbit[T_DIM * BW_DIM];

// Fused pack+transpose: one warp per 32b x 32t tile.
// 32 coalesced 128B loads -> 32 ballots (row words) -> 32 ballots (transpose).
__global__ void pack_transpose_kernel(const int* __restrict__ in) {
    int tile = blockIdx.x * (blockDim.x >> 5) + (threadIdx.x >> 5);
    int lane = threadIdx.x & 31;
    if (tile >= BW_DIM * (T_DIM / 32)) return;
    int bb = tile >> 7;             // tile / 128  : which 32-batch group
    int wt = tile & 127;            // tile % 128  : which 32-t group

    // Row words: rw (on lane i) = bits over t for b = bb*32+i
    unsigned rw = 0;
#pragma unroll
    for (int i = 0; i < 32; ++i) {
        unsigned w = __ballot_sync(0xFFFFFFFFu,
                       in[(size_t)(bb * 32 + i) * T_DIM + wt * 32 + lane] != 0);
        if (lane == i) rw = w;
    }
    // Transpose: col_j = word over b for t = wt*32 + j
    unsigned mine = 0;
#pragma unroll
    for (int j = 0; j < 32; ++j) {
        unsigned col = __ballot_sync(0xFFFFFFFFu, (rw >> j) & 1u);
        if (lane == j) mine = col;
    }
    tbit[(size_t)(wt * 32 + lane) * BW_DIM + bb] = mine;
}

__device__ __forceinline__ int ldcg_i32(const int* p) {
    int v;
    asm volatile("ld.global.cg.b32 %0, [%1];" : "=r"(v) : "l"(p));
    return v;
}
__device__ __forceinline__ void stcg_f32(float* p, float v) {
    asm volatile("st.global.cg.f32 [%0], %1;" :: "l"(p), "f"(v));
}

// One CTA per neuron: build all B addresses, counting-sort by DRAM row
// (addr>>8), issue gathers in row-sorted order so same-row requests are
// temporally adjacent at the memory controller (row hits, fewer activates).
__global__ __launch_bounds__(GTHREADS)
void ram_gather_kernel(const int* __restrict__ conn,     // [N, K]
                       const int* __restrict__ memory,   // [N, M]
                       float*     __restrict__ out)      // [B, N]
{
    const int n    = blockIdx.x;
    const int tid  = threadIdx.x;
    const int lane = tid & 31;

    __shared__ int      sc[K_DIM];
    __shared__ unsigned cnt[256];
    __shared__ unsigned scn[256];
    __shared__ unsigned head[256];
    __shared__ unsigned short sortedA[B_DIM];
    __shared__ unsigned short sortedB[B_DIM];

    if (tid < K_DIM) sc[tid] = conn[n * K_DIM + tid];
    if (tid < 256) cnt[tid] = 0;
    __syncthreads();

    // ---- Build addresses: warp = 32 consecutive b sharing one b-word ----
    unsigned myA[B_DIM / GTHREADS];   // 2 items per thread
    unsigned myB[B_DIM / GTHREADS];
#pragma unroll
    for (int j = 0; j < B_DIM / GTHREADS; ++j) {
        int b  = j * GTHREADS + tid;
        int bw = b >> 5;
        unsigned w16 = 0;
        if (lane < K_DIM) w16 = __ldg(&tbit[sc[lane] * BW_DIM + bw]);
        unsigned a = 0;
#pragma unroll
        for (int k = 0; k < K_DIM; ++k) {
            unsigned wk = __shfl_sync(0xFFFFFFFFu, w16, k);
            a |= ((wk >> lane) & 1u) << k;
        }
        myA[j] = a;
        myB[j] = (unsigned)b;
        atomicAdd(&cnt[a >> 8], 1u);
    }
    __syncthreads();

    // ---- Inclusive scan of 256 counts ----
    if (tid < 256) scn[tid] = cnt[tid];
    __syncthreads();
    for (int d = 1; d < 256; d <<= 1) {
        unsigned v = 0;
        if (tid < 256 && tid >= d) v = scn[tid - d];
        __syncthreads();
        if (tid < 256) scn[tid] += v;
        __syncthreads();
    }
    if (tid < 256) head[tid] = scn[tid] - cnt[tid];
    __syncthreads();

    // ---- Place items into row-sorted order ----
#pragma unroll
    for (int j = 0; j < B_DIM / GTHREADS; ++j) {
        unsigned pos = atomicAdd(&head[myA[j] >> 8], 1u);
        sortedA[pos] = (unsigned short)myA[j];
        sortedB[pos] = (unsigned short)myB[j];
    }
    __syncthreads();

    // ---- Row-sorted gather: both loads issued before either store ----
    const int* mrow = memory + ((size_t)n << 16);
    unsigned a0 = sortedA[tid],            b0 = sortedB[tid];
    unsigned a1 = sortedA[GTHREADS + tid], b1 = sortedB[GTHREADS + tid];
    int v0 = ldcg_i32(mrow + a0);
    int v1 = ldcg_i32(mrow + a1);
    stcg_f32(out + (size_t)b0 * N_DIM + n, (float)(v0 & 1));
    stcg_f32(out + (size_t)b1 * N_DIM + n, (float)(v1 & 1));
}

extern "C" void kernel_launch(void* const* d_in, const int* in_sizes, int n_in,
                              void* d_out, int out_size) {
    // Identify inputs by unique element counts (robust to metadata order)
    const int* input_bits  = nullptr;
    const int* connections = nullptr;
    const int* memory      = nullptr;

    for (int i = 0; i < n_in; ++i) {
        long long s = in_sizes[i];
        if (s == (long long)N_DIM * K_DIM)            connections = (const int*)d_in[i];
        else if (s == (long long)N_DIM * 65536LL)     memory      = (const int*)d_in[i];
        else                                          input_bits  = (const int*)d_in[i];
    }

    // 32B L2 fetch granularity (measured: gather DRAM traffic 248->88MB).
    cudaStreamCaptureStatus cap = cudaStreamCaptureStatusNone;
    cudaStreamIsCapturing((cudaStream_t)0, &cap);
    if (cap == cudaStreamCaptureStatusNone) {
        cudaDeviceSetLimit(cudaLimitMaxL2FetchGranularity, 32);
        cudaGetLastError();
    }

    // Fused pack+transpose: 4096 warp-tiles, 8 warps per block
    pack_transpose_kernel<<<(BW_DIM * (T_DIM / 32)) / 8, 256>>>(input_bits);
    // Row-sorted gather, one CTA per neuron
    ram_gather_kernel<<<N_DIM, GTHREADS>>>(connections, memory, (float*)d_out);
}

// round 12
// speedup vs baseline: 1.6862x; 1.0691x over previous
#include <cuda_runtime.h>
#include <cstdint>

// Problem constants (B=1024, T=4096, N=2048, K=16, M=2^16)
#define T_DIM   4096
#define N_DIM   2048
#define K_DIM   16
#define B_DIM   1024
#define BW_DIM  (B_DIM / 32)     // 32 b-words per bit-plane
#define GTHREADS 512

// Bit-plane transposed input: tbit[t][bw], bit (b&31) = input[b][t]. 512 KB.
__device__ unsigned tbit[T_DIM * BW_DIM];
// Bit-packed result: outbitT[n][w], bit (b&31) of word w = result(b=w*32+bit, n). 256 KB.
__device__ unsigned outbitT[N_DIM * BW_DIM];

// Fused pack+transpose: one warp per 32b x 32t tile.
__global__ void pack_transpose_kernel(const int* __restrict__ in) {
    int tile = blockIdx.x * (blockDim.x >> 5) + (threadIdx.x >> 5);
    int lane = threadIdx.x & 31;
    if (tile >= BW_DIM * (T_DIM / 32)) return;
    int bb = tile >> 7;             // which 32-batch group
    int wt = tile & 127;            // which 32-t group

    unsigned rw = 0;
#pragma unroll
    for (int i = 0; i < 32; ++i) {
        unsigned w = __ballot_sync(0xFFFFFFFFu,
                       in[(size_t)(bb * 32 + i) * T_DIM + wt * 32 + lane] != 0);
        if (lane == i) rw = w;
    }
    unsigned mine = 0;
#pragma unroll
    for (int j = 0; j < 32; ++j) {
        unsigned col = __ballot_sync(0xFFFFFFFFu, (rw >> j) & 1u);
        if (lane == j) mine = col;
    }
    tbit[(size_t)(wt * 32 + lane) * BW_DIM + bb] = mine;
}

__device__ __forceinline__ int ldcg_i32(const int* p) {
    int v;
    asm volatile("ld.global.cg.b32 %0, [%1];" : "=r"(v) : "l"(p));
    return v;
}

// One CTA per neuron: counting-sort addresses by DRAM row (addr>>8), issue
// gathers row-sorted (temporal row clustering), emit results BIT-PACKED
// (32 word-stores per CTA instead of 1024 scatter stores).
__global__ __launch_bounds__(GTHREADS)
void ram_gather_kernel(const int* __restrict__ conn,     // [N, K]
                       const int* __restrict__ memory)   // [N, M]
{
    const int n    = blockIdx.x;
    const int tid  = threadIdx.x;
    const int lane = tid & 31;
    const int warp = tid >> 5;

    __shared__ int      sc[K_DIM];
    __shared__ unsigned cnt[256];
    __shared__ unsigned scn[256];
    __shared__ unsigned head[256];
    __shared__ unsigned short sortedA[B_DIM];
    __shared__ unsigned short sortedB[B_DIM];
    __shared__ unsigned char  res[B_DIM];

    if (tid < K_DIM) sc[tid] = conn[n * K_DIM + tid];
    if (tid < 256) cnt[tid] = 0;
    __syncthreads();

    // ---- Build addresses: warp = 32 consecutive b sharing one b-word ----
    unsigned myA[B_DIM / GTHREADS];   // 2 items per thread
    unsigned myB[B_DIM / GTHREADS];
#pragma unroll
    for (int j = 0; j < B_DIM / GTHREADS; ++j) {
        int b  = j * GTHREADS + tid;
        int bw = b >> 5;
        unsigned w16 = 0;
        if (lane < K_DIM) w16 = __ldg(&tbit[sc[lane] * BW_DIM + bw]);
        unsigned a = 0;
#pragma unroll
        for (int k = 0; k < K_DIM; ++k) {
            unsigned wk = __shfl_sync(0xFFFFFFFFu, w16, k);
            a |= ((wk >> lane) & 1u) << k;
        }
        myA[j] = a;
        myB[j] = (unsigned)b;
        atomicAdd(&cnt[a >> 8], 1u);
    }
    __syncthreads();

    // ---- Inclusive scan of 256 counts ----
    if (tid < 256) scn[tid] = cnt[tid];
    __syncthreads();
    for (int d = 1; d < 256; d <<= 1) {
        unsigned v = 0;
        if (tid < 256 && tid >= d) v = scn[tid - d];
        __syncthreads();
        if (tid < 256) scn[tid] += v;
        __syncthreads();
    }
    if (tid < 256) head[tid] = scn[tid] - cnt[tid];
    __syncthreads();

    // ---- Place items into row-sorted order ----
#pragma unroll
    for (int j = 0; j < B_DIM / GTHREADS; ++j) {
        unsigned pos = atomicAdd(&head[myA[j] >> 8], 1u);
        sortedA[pos] = (unsigned short)myA[j];
        sortedB[pos] = (unsigned short)myB[j];
    }
    __syncthreads();

    // ---- Row-sorted gather; results staged as smem bytes (no scatter STG) ----
    const int* mrow = memory + ((size_t)n << 16);
    unsigned a0 = sortedA[tid],            b0 = sortedB[tid];
    unsigned a1 = sortedA[GTHREADS + tid], b1 = sortedB[GTHREADS + tid];
    int v0 = ldcg_i32(mrow + a0);
    int v1 = ldcg_i32(mrow + a1);
    res[b0] = (unsigned char)(v0 & 1);
    res[b1] = (unsigned char)(v1 & 1);
    __syncthreads();

    // ---- Bit-pack: 32 words, each warp handles 2 ----
    for (int w = warp; w < BW_DIM; w += GTHREADS / 32) {
        unsigned word = __ballot_sync(0xFFFFFFFFu, res[w * 32 + lane] != 0);
        if (lane == 0) outbitT[n * BW_DIM + w] = word;
    }
}

// Expand + transpose: one warp per 32n x 32b bit tile -> coalesced float out.
__global__ void expand_kernel(float* __restrict__ out) {
    int tile = blockIdx.x * (blockDim.x >> 5) + (threadIdx.x >> 5);
    int lane = threadIdx.x & 31;
    if (tile >= (N_DIM / 32) * BW_DIM) return;
    int nn = tile >> 5;             // tile / 32 : which 32-neuron group
    int bb = tile & 31;             // tile % 32 : which 32-batch word

    // rw (lane l) = result bits over b for n = nn*32 + l
    unsigned rw = outbitT[(nn * 32 + lane) * BW_DIM + bb];
#pragma unroll
    for (int j = 0; j < 32; ++j) {
        unsigned col = __ballot_sync(0xFFFFFFFFu, (rw >> j) & 1u); // over n-lanes, b fixed
        out[(size_t)(bb * 32 + j) * N_DIM + nn * 32 + lane] = (float)((col >> lane) & 1u);
    }
}

extern "C" void kernel_launch(void* const* d_in, const int* in_sizes, int n_in,
                              void* d_out, int out_size) {
    const int* input_bits  = nullptr;
    const int* connections = nullptr;
    const int* memory      = nullptr;

    for (int i = 0; i < n_in; ++i) {
        long long s = in_sizes[i];
        if (s == (long long)N_DIM * K_DIM)            connections = (const int*)d_in[i];
        else if (s == (long long)N_DIM * 65536LL)     memory      = (const int*)d_in[i];
        else                                          input_bits  = (const int*)d_in[i];
    }

    // 32B L2 fetch granularity (measured: gather DRAM traffic 248->88MB).
    cudaStreamCaptureStatus cap = cudaStreamCaptureStatusNone;
    cudaStreamIsCapturing((cudaStream_t)0, &cap);
    if (cap == cudaStreamCaptureStatusNone) {
        cudaDeviceSetLimit(cudaLimitMaxL2FetchGranularity, 32);
        cudaGetLastError();
    }

    pack_transpose_kernel<<<(BW_DIM * (T_DIM / 32)) / 8, 256>>>(input_bits);
    ram_gather_kernel<<<N_DIM, GTHREADS>>>(connections, memory);
    expand_kernel<<<((N_DIM / 32) * BW_DIM) / 8, 256>>>((float*)d_out);
}

// round 13
// speedup vs baseline: 1.8128x; 1.0751x over previous
#include <cuda_runtime.h>
#include <cstdint>

// Problem constants (B=1024, T=4096, N=2048, K=16, M=2^16)
#define T_DIM   4096
#define N_DIM   2048
#define K_DIM   16
#define B_DIM   1024
#define BW_DIM  (B_DIM / 32)     // 32 b-words per bit-plane
#define GTHREADS 512

// Bit-plane transposed input: tbit[t][bw], bit (b&31) = input[b][t]. 512 KB.
__device__ unsigned tbit[T_DIM * BW_DIM];
// Bit-packed result: outbitT[n][w], bit (b&31) of word w = result(b, n). 256 KB.
__device__ unsigned outbitT[N_DIM * BW_DIM];

// 5-stage warp bit-matrix transpose (32x32). Lane l holds row word x_l
// (bit j = M[l][j]); returns lane l holding column word (bit j = M[j][l]).
__device__ __forceinline__ unsigned warp_bit_transpose(unsigned x, int lane) {
#pragma unroll
    for (int k = 16; k >= 1; k >>= 1) {
        unsigned mask = (k == 16) ? 0xFFFF0000u :
                        (k ==  8) ? 0xFF00FF00u :
                        (k ==  4) ? 0xF0F0F0F0u :
                        (k ==  2) ? 0xCCCCCCCCu : 0xAAAAAAAAu;
        unsigned y = __shfl_xor_sync(0xFFFFFFFFu, x, k);
        if ((lane & k) == 0) x = (x & ~mask) | ((y << k) &  mask);
        else                 x = (x &  mask) | ((y >> k) & ~mask);
    }
    return x;
}

// Fused pack+transpose: one warp per 32b x 32t tile.
// 32 batched coalesced loads -> 32 ballots -> 5-shuffle transpose -> 1 store.
__global__ void pack_transpose_kernel(const int* __restrict__ in) {
    int tile = blockIdx.x * (blockDim.x >> 5) + (threadIdx.x >> 5);
    int lane = threadIdx.x & 31;
    if (tile >= BW_DIM * (T_DIM / 32)) return;
    int bb = tile >> 7;             // which 32-batch group
    int wt = tile & 127;            // which 32-t group

    // Batch all 32 loads (independent -> full MLP)
    int v[32];
    const int* base = in + (size_t)(bb * 32) * T_DIM + wt * 32 + lane;
#pragma unroll
    for (int i = 0; i < 32; ++i) v[i] = base[(size_t)i * T_DIM];

    // Row words: rw on lane i = bits over t for b = bb*32+i
    unsigned rw = 0;
#pragma unroll
    for (int i = 0; i < 32; ++i) {
        unsigned w = __ballot_sync(0xFFFFFFFFu, v[i] != 0);
        if (lane == i) rw = w;
    }
    // Transpose in-register: lane l -> word over b for t = wt*32 + l
    unsigned mine = warp_bit_transpose(rw, lane);
    tbit[(size_t)(wt * 32 + lane) * BW_DIM + bb] = mine;
}

__device__ __forceinline__ int ldcg_i32(const int* p) {
    int v;
    asm volatile("ld.global.cg.b32 %0, [%1];" : "=r"(v) : "l"(p));
    return v;
}

// One CTA per neuron: counting-sort addresses by DRAM row (addr>>8), issue
// gathers row-sorted (temporal row clustering), bit-packed result emission.
__global__ __launch_bounds__(GTHREADS)
void ram_gather_kernel(const int* __restrict__ conn,     // [N, K]
                       const int* __restrict__ memory)   // [N, M]
{
    const int n    = blockIdx.x;
    const int tid  = threadIdx.x;
    const int lane = tid & 31;
    const int warp = tid >> 5;

    __shared__ int      sc[K_DIM];
    __shared__ unsigned cnt[256];
    __shared__ unsigned head[256];
    __shared__ unsigned wsum[8];
    __shared__ unsigned short sortedA[B_DIM];
    __shared__ unsigned short sortedB[B_DIM];
    __shared__ unsigned char  res[B_DIM];

    if (tid < K_DIM) sc[tid] = conn[n * K_DIM + tid];
    if (tid < 256) cnt[tid] = 0;
    __syncthreads();

    // ---- Build addresses: warp = 32 consecutive b sharing one b-word ----
    unsigned myA[B_DIM / GTHREADS];   // 2 items per thread
    unsigned myB[B_DIM / GTHREADS];
#pragma unroll
    for (int j = 0; j < B_DIM / GTHREADS; ++j) {
        int b  = j * GTHREADS + tid;
        int bw = b >> 5;
        unsigned w16 = 0;
        if (lane < K_DIM) w16 = __ldg(&tbit[sc[lane] * BW_DIM + bw]);
        unsigned a = 0;
#pragma unroll
        for (int k = 0; k < K_DIM; ++k) {
            unsigned wk = __shfl_sync(0xFFFFFFFFu, w16, k);
            a |= ((wk >> lane) & 1u) << k;
        }
        myA[j] = a;
        myB[j] = (unsigned)b;
        atomicAdd(&cnt[a >> 8], 1u);
    }
    __syncthreads();

    // ---- Exclusive scan of 256 counts: warp-shuffle scan, 2 barriers ----
    if (tid < 256) {
        unsigned v = cnt[tid];
        unsigned s = v;
#pragma unroll
        for (int d = 1; d < 32; d <<= 1) {
            unsigned t = __shfl_up_sync(0xFFFFFFFFu, s, d);
            if (lane >= d) s += t;
        }
        if (lane == 31) wsum[warp] = s;          // warp totals (warps 0..7)
        // stash inclusive-within-warp minus own value (exclusive part)
        head[tid] = s - v;
    }
    __syncthreads();
    if (tid < 256) {
        unsigned off = 0;
#pragma unroll
        for (int w = 0; w < 8; ++w) off += (w < warp) ? wsum[w] : 0u;
        head[tid] += off;                         // exclusive global start
    }
    __syncthreads();

    // ---- Place items into row-sorted order ----
#pragma unroll
    for (int j = 0; j < B_DIM / GTHREADS; ++j) {
        unsigned pos = atomicAdd(&head[myA[j] >> 8], 1u);
        sortedA[pos] = (unsigned short)myA[j];
        sortedB[pos] = (unsigned short)myB[j];
    }
    __syncthreads();

    // ---- Row-sorted gather; results staged as smem bytes ----
    const int* mrow = memory + ((size_t)n << 16);
    unsigned a0 = sortedA[tid],            b0 = sortedB[tid];
    unsigned a1 = sortedA[GTHREADS + tid], b1 = sortedB[GTHREADS + tid];
    int v0 = ldcg_i32(mrow + a0);
    int v1 = ldcg_i32(mrow + a1);
    res[b0] = (unsigned char)(v0 & 1);
    res[b1] = (unsigned char)(v1 & 1);
    __syncthreads();

    // ---- Bit-pack: 32 words, each warp handles 2 ----
    for (int w = warp; w < BW_DIM; w += GTHREADS / 32) {
        unsigned word = __ballot_sync(0xFFFFFFFFu, res[w * 32 + lane] != 0);
        if (lane == 0) outbitT[n * BW_DIM + w] = word;
    }
}

// Expand + transpose: one warp per 32n x 32b bit tile -> coalesced float out.
__global__ void expand_kernel(float* __restrict__ out) {
    int tile = blockIdx.x * (blockDim.x >> 5) + (threadIdx.x >> 5);
    int lane = threadIdx.x & 31;
    if (tile >= (N_DIM / 32) * BW_DIM) return;
    int nn = tile >> 5;             // which 32-neuron group
    int bb = tile & 31;             // which 32-batch word

    // rw lane l: bit j = result(b=bb*32+j, n=nn*32+l)
    unsigned rw = outbitT[(nn * 32 + lane) * BW_DIM + bb];
    // Transpose: lane l -> bit j = result(b=bb*32+l, n=nn*32+j)
    unsigned tx = warp_bit_transpose(rw, lane);
#pragma unroll
    for (int j = 0; j < 32; ++j) {
        unsigned wj = __shfl_sync(0xFFFFFFFFu, tx, j);  // b = bb*32+j row over n
        out[(size_t)(bb * 32 + j) * N_DIM + nn * 32 + lane] = (float)((wj >> lane) & 1u);
    }
}

extern "C" void kernel_launch(void* const* d_in, const int* in_sizes, int n_in,
                              void* d_out, int out_size) {
    const int* input_bits  = nullptr;
    const int* connections = nullptr;
    const int* memory      = nullptr;

    for (int i = 0; i < n_in; ++i) {
        long long s = in_sizes[i];
        if (s == (long long)N_DIM * K_DIM)            connections = (const int*)d_in[i];
        else if (s == (long long)N_DIM * 65536LL)     memory      = (const int*)d_in[i];
        else                                          input_bits  = (const int*)d_in[i];
    }

    // 32B L2 fetch granularity (measured: gather DRAM traffic 248->88MB).
    cudaStreamCaptureStatus cap = cudaStreamCaptureStatusNone;
    cudaStreamIsCapturing((cudaStream_t)0, &cap);
    if (cap == cudaStreamCaptureStatusNone) {
        cudaDeviceSetLimit(cudaLimitMaxL2FetchGranularity, 32);
        cudaGetLastError();
    }

    pack_transpose_kernel<<<(BW_DIM * (T_DIM / 32)) / 8, 256>>>(input_bits);
    ram_gather_kernel<<<N_DIM, GTHREADS>>>(connections, memory);
    expand_kernel<<<((N_DIM / 32) * BW_DIM) / 8, 256>>>((float*)d_out);
}

// round 14
// speedup vs baseline: 2.0326x; 1.1213x over previous
#include <cuda_runtime.h>
#include <cstdint>

// Problem constants (B=1024, T=4096, N=2048, K=16, M=2^16)
#define T_DIM   4096
#define N_DIM   2048
#define K_DIM   16
#define B_DIM   1024
#define BW_DIM  (B_DIM / 32)     // 32 b-words per bit-plane
#define GTHREADS 512

// Bit-plane transposed input, layout [bw][t]: tbit[bw*T + t], bit (b&31) = input[b][t].
__device__ unsigned tbit[BW_DIM * T_DIM];
// Bit-packed result: outbitT[n][w], bit (b&31) of word w = result(b, n). 256 KB.
__device__ unsigned outbitT[N_DIM * BW_DIM];

// 5-stage warp bit-matrix transpose (32x32).
__device__ __forceinline__ unsigned warp_bit_transpose(unsigned x, int lane) {
#pragma unroll
    for (int k = 16; k >= 1; k >>= 1) {
        unsigned mask = (k == 16) ? 0xFFFF0000u :
                        (k ==  8) ? 0xFF00FF00u :
                        (k ==  4) ? 0xF0F0F0F0u :
                        (k ==  2) ? 0xCCCCCCCCu : 0xAAAAAAAAu;
        unsigned y = __shfl_xor_sync(0xFFFFFFFFu, x, k);
        if ((lane & k) == 0) x = (x & ~mask) | ((y << k) &  mask);
        else                 x = (x &  mask) | ((y >> k) & ~mask);
    }
    return x;
}

// Pack v3: one warp per 16b x 32t HALF-tile (2x warps of v2 -> occ ~85%).
// 16 batched loads -> 16 ballots -> transpose -> coalesced ushort store.
__global__ void pack_transpose_kernel(const int* __restrict__ in) {
    int ht   = blockIdx.x * (blockDim.x >> 5) + (threadIdx.x >> 5);
    int lane = threadIdx.x & 31;
    if (ht >= BW_DIM * (T_DIM / 32) * 2) return;
    int half = ht & 1;
    int tile = ht >> 1;
    int bb = tile >> 7;             // which 32-batch group
    int wt = tile & 127;            // which 32-t group
    int b0 = bb * 32 + half * 16;

    int v[16];
    const int* base = in + (size_t)b0 * T_DIM + wt * 32 + lane;
#pragma unroll
    for (int i = 0; i < 16; ++i) v[i] = base[(size_t)i * T_DIM];

    unsigned rw = 0;                 // lanes 16..31 stay 0
#pragma unroll
    for (int i = 0; i < 16; ++i) {
        unsigned w = __ballot_sync(0xFFFFFFFFu, v[i] != 0);
        if (lane == i) rw = w;
    }
    unsigned tx = warp_bit_transpose(rw, lane);   // low 16 bits valid
    // word index (layout [bw][t]) = bb*T + wt*32 + lane  -> consecutive per lane
    size_t word = (size_t)bb * T_DIM + wt * 32 + lane;
    ((unsigned short*)tbit)[word * 2 + half] = (unsigned short)(tx & 0xFFFFu);
}

__device__ __forceinline__ int ldcg_i32(const int* p) {
    int v;
    asm volatile("ld.global.cg.b32 %0, [%1];" : "=r"(v) : "l"(p));
    return v;
}

// One CTA per neuron: counting-sort addresses by DRAM row (addr>>8), issue
// gathers row-sorted (temporal row clustering), bit-packed result emission.
__global__ __launch_bounds__(GTHREADS)
void ram_gather_kernel(const int* __restrict__ conn,     // [N, K]
                       const int* __restrict__ memory)   // [N, M]
{
    const int n    = blockIdx.x;
    const int tid  = threadIdx.x;
    const int lane = tid & 31;
    const int warp = tid >> 5;

    __shared__ int      sc[K_DIM];
    __shared__ unsigned cnt[256];
    __shared__ unsigned head[256];
    __shared__ unsigned wsum[8];
    __shared__ unsigned sorted[B_DIM];      // (b<<16) | addr
    __shared__ unsigned char res[B_DIM];

    if (tid < K_DIM) sc[tid] = conn[n * K_DIM + tid];
    if (tid < 256) cnt[tid] = 0;
    __syncthreads();

    // ---- Build addresses: warp = 32 consecutive b sharing one bw ----
    unsigned myA[B_DIM / GTHREADS];   // 2 items per thread
#pragma unroll
    for (int j = 0; j < B_DIM / GTHREADS; ++j) {
        int b  = j * GTHREADS + tid;
        int bw = b >> 5;
        unsigned w16 = 0;
        if (lane < K_DIM) w16 = __ldg(&tbit[(size_t)bw * T_DIM + sc[lane]]);
        unsigned a = 0;
#pragma unroll
        for (int k = 0; k < K_DIM; ++k) {
            unsigned wk = __shfl_sync(0xFFFFFFFFu, w16, k);
            a |= ((wk >> lane) & 1u) << k;
        }
        myA[j] = ((unsigned)b << 16) | a;
        atomicAdd(&cnt[a >> 8], 1u);
    }
    __syncthreads();

    // ---- Exclusive scan of 256 counts: warp-shuffle scan ----
    if (tid < 256) {
        unsigned v = cnt[tid];
        unsigned s = v;
#pragma unroll
        for (int d = 1; d < 32; d <<= 1) {
            unsigned t = __shfl_up_sync(0xFFFFFFFFu, s, d);
            if (lane >= d) s += t;
        }
        if (lane == 31) wsum[warp] = s;
        head[tid] = s - v;
    }
    __syncthreads();
    if (tid < 256) {
        unsigned off = 0;
#pragma unroll
        for (int w = 0; w < 8; ++w) off += (w < warp) ? wsum[w] : 0u;
        head[tid] += off;
    }
    __syncthreads();

    // ---- Place items into row-sorted order ----
#pragma unroll
    for (int j = 0; j < B_DIM / GTHREADS; ++j) {
        unsigned pos = atomicAdd(&head[(myA[j] & 0xFFFFu) >> 8], 1u);
        sorted[pos] = myA[j];
    }
    __syncthreads();

    // ---- Row-sorted gather; results staged as smem bytes ----
    const int* mrow = memory + ((size_t)n << 16);
    unsigned s0 = sorted[tid];
    unsigned s1 = sorted[GTHREADS + tid];
    int v0 = ldcg_i32(mrow + (s0 & 0xFFFFu));
    int v1 = ldcg_i32(mrow + (s1 & 0xFFFFu));
    res[s0 >> 16] = (unsigned char)(v0 & 1);
    res[s1 >> 16] = (unsigned char)(v1 & 1);
    __syncthreads();

    // ---- Bit-pack: 32 words, each warp handles 2 ----
    for (int w = warp; w < BW_DIM; w += GTHREADS / 32) {
        unsigned word = __ballot_sync(0xFFFFFFFFu, res[w * 32 + lane] != 0);
        if (lane == 0) outbitT[n * BW_DIM + w] = word;
    }
}

// Expand + transpose: one warp per 32n x 32b bit tile -> coalesced float out.
__global__ void expand_kernel(float* __restrict__ out) {
    int tile = blockIdx.x * (blockDim.x >> 5) + (threadIdx.x >> 5);
    int lane = threadIdx.x & 31;
    if (tile >= (N_DIM / 32) * BW_DIM) return;
    int nn = tile >> 5;
    int bb = tile & 31;

    unsigned rw = outbitT[(nn * 32 + lane) * BW_DIM + bb];
    unsigned tx = warp_bit_transpose(rw, lane);
#pragma unroll
    for (int j = 0; j < 32; ++j) {
        unsigned wj = __shfl_sync(0xFFFFFFFFu, tx, j);
        out[(size_t)(bb * 32 + j) * N_DIM + nn * 32 + lane] = (float)((wj >> lane) & 1u);
    }
}

extern "C" void kernel_launch(void* const* d_in, const int* in_sizes, int n_in,
                              void* d_out, int out_size) {
    const int* input_bits  = nullptr;
    const int* connections = nullptr;
    const int* memory      = nullptr;

    for (int i = 0; i < n_in; ++i) {
        long long s = in_sizes[i];
        if (s == (long long)N_DIM * K_DIM)            connections = (const int*)d_in[i];
        else if (s == (long long)N_DIM * 65536LL)     memory      = (const int*)d_in[i];
        else                                          input_bits  = (const int*)d_in[i];
    }

    // 32B L2 fetch granularity (measured: gather DRAM traffic 248->88MB).
    cudaStreamCaptureStatus cap = cudaStreamCaptureStatusNone;
    cudaStreamIsCapturing((cudaStream_t)0, &cap);
    if (cap == cudaStreamCaptureStatusNone) {
        cudaDeviceSetLimit(cudaLimitMaxL2FetchGranularity, 32);
        cudaGetLastError();
    }

    // Pack v3: 8192 half-tile warps, 8 warps per block
    pack_transpose_kernel<<<(BW_DIM * (T_DIM / 32) * 2) / 8, 256>>>(input_bits);
    ram_gather_kernel<<<N_DIM, GTHREADS>>>(connections, memory);
    expand_kernel<<<((N_DIM / 32) * BW_DIM) / 8, 256>>>((float*)d_out);
}

// round 15
// speedup vs baseline: 2.0606x; 1.0138x over previous
#include <cuda_runtime.h>
#include <cstdint>

// Problem constants (B=1024, T=4096, N=2048, K=16, M=2^16)
#define T_DIM   4096
#define N_DIM   2048
#define K_DIM   16
#define B_DIM   1024
#define BW_DIM  (B_DIM / 32)     // 32 b-words per bit-plane
#define GTHREADS 512

// Bit-plane transposed input, layout [bw][t]: tbit[bw*T + t], bit (b&31) = input[b][t].
__device__ unsigned tbit[BW_DIM * T_DIM];
// Bit-packed result: outbitT[n][w], bit (b&31) of word w = result(b, n). 256 KB.
__device__ unsigned outbitT[N_DIM * BW_DIM];

// 5-stage warp bit-matrix transpose (32x32). Lane l holds row word x_l
// (bit j = M[l][j]); returns lane l holding column word (bit j = M[j][l]).
__device__ __forceinline__ unsigned warp_bit_transpose(unsigned x, int lane) {
#pragma unroll
    for (int k = 16; k >= 1; k >>= 1) {
        unsigned mask = (k == 16) ? 0xFFFF0000u :
                        (k ==  8) ? 0xFF00FF00u :
                        (k ==  4) ? 0xF0F0F0F0u :
                        (k ==  2) ? 0xCCCCCCCCu : 0xAAAAAAAAu;
        unsigned y = __shfl_xor_sync(0xFFFFFFFFu, x, k);
        if ((lane & k) == 0) x = (x & ~mask) | ((y << k) &  mask);
        else                 x = (x &  mask) | ((y >> k) & ~mask);
    }
    return x;
}

// Pack v3: one warp per 16b x 32t HALF-tile.
__global__ void pack_transpose_kernel(const int* __restrict__ in) {
    int ht   = blockIdx.x * (blockDim.x >> 5) + (threadIdx.x >> 5);
    int lane = threadIdx.x & 31;
    if (ht >= BW_DIM * (T_DIM / 32) * 2) return;
    int half = ht & 1;
    int tile = ht >> 1;
    int bb = tile >> 7;             // which 32-batch group
    int wt = tile & 127;            // which 32-t group
    int b0 = bb * 32 + half * 16;

    int v[16];
    const int* base = in + (size_t)b0 * T_DIM + wt * 32 + lane;
#pragma unroll
    for (int i = 0; i < 16; ++i) v[i] = base[(size_t)i * T_DIM];

    unsigned rw = 0;                 // lanes 16..31 stay 0
#pragma unroll
    for (int i = 0; i < 16; ++i) {
        unsigned w = __ballot_sync(0xFFFFFFFFu, v[i] != 0);
        if (lane == i) rw = w;
    }
    unsigned tx = warp_bit_transpose(rw, lane);   // low 16 bits valid
    size_t word = (size_t)bb * T_DIM + wt * 32 + lane;
    ((unsigned short*)tbit)[word * 2 + half] = (unsigned short)(tx & 0xFFFFu);
}

__device__ __forceinline__ int ldcg_i32(const int* p) {
    int v;
    asm volatile("ld.global.cg.b32 %0, [%1];" : "=r"(v) : "l"(p));
    return v;
}

// One CTA per neuron. Address build is now a single warp bit-transpose:
// lane k (k<16) holds tbit word for connection k; transposing the 16x32 bit
// matrix puts each lane's 16-bit table address directly in its register.
__global__ __launch_bounds__(GTHREADS)
void ram_gather_kernel(const int* __restrict__ conn,     // [N, K]
                       const int* __restrict__ memory)   // [N, M]
{
    const int n    = blockIdx.x;
    const int tid  = threadIdx.x;
    const int lane = tid & 31;
    const int warp = tid >> 5;

    __shared__ int      sc[K_DIM];
    __shared__ unsigned cnt[256];
    __shared__ unsigned head[256];
    __shared__ unsigned wsum[8];
    __shared__ unsigned sorted[B_DIM];      // (b<<16) | addr
    __shared__ unsigned char res[B_DIM];

    if (tid < K_DIM) sc[tid] = conn[n * K_DIM + tid];
    if (tid < 256) cnt[tid] = 0;
    __syncthreads();

    // ---- Build addresses: ONE bit-transpose per 32 batch items ----
    unsigned myA[B_DIM / GTHREADS];   // 2 items per thread
#pragma unroll
    for (int j = 0; j < B_DIM / GTHREADS; ++j) {
        int b  = j * GTHREADS + tid;
        int bw = b >> 5;                       // constant per warp
        unsigned w16 = 0;
        if (lane < K_DIM) w16 = __ldg(&tbit[(size_t)bw * T_DIM + sc[lane]]);
        unsigned a = warp_bit_transpose(w16, lane) & 0xFFFFu;
        myA[j] = ((unsigned)b << 16) | a;
        atomicAdd(&cnt[a >> 8], 1u);
    }
    __syncthreads();

    // ---- Exclusive scan of 256 counts: warp-shuffle scan ----
    if (tid < 256) {
        unsigned v = cnt[tid];
        unsigned s = v;
#pragma unroll
        for (int d = 1; d < 32; d <<= 1) {
            unsigned t = __shfl_up_sync(0xFFFFFFFFu, s, d);
            if (lane >= d) s += t;
        }
        if (lane == 31) wsum[warp] = s;
        head[tid] = s - v;
    }
    __syncthreads();
    if (tid < 256) {
        unsigned off = 0;
#pragma unroll
        for (int w = 0; w < 8; ++w) off += (w < warp) ? wsum[w] : 0u;
        head[tid] += off;
    }
    __syncthreads();

    // ---- Place items into row-sorted order ----
#pragma unroll
    for (int j = 0; j < B_DIM / GTHREADS; ++j) {
        unsigned pos = atomicAdd(&head[(myA[j] & 0xFFFFu) >> 8], 1u);
        sorted[pos] = myA[j];
    }
    __syncthreads();

    // ---- Row-sorted gather; results staged as smem bytes ----
    const int* mrow = memory + ((size_t)n << 16);
    unsigned s0 = sorted[tid];
    unsigned s1 = sorted[GTHREADS + tid];
    int v0 = ldcg_i32(mrow + (s0 & 0xFFFFu));
    int v1 = ldcg_i32(mrow + (s1 & 0xFFFFu));
    res[s0 >> 16] = (unsigned char)(v0 & 1);
    res[s1 >> 16] = (unsigned char)(v1 & 1);
    __syncthreads();

    // ---- Bit-pack: 32 words, each warp handles 2 ----
    for (int w = warp; w < BW_DIM; w += GTHREADS / 32) {
        unsigned word = __ballot_sync(0xFFFFFFFFu, res[w * 32 + lane] != 0);
        if (lane == 0) outbitT[n * BW_DIM + w] = word;
    }
}

// Expand + transpose: one warp per 32n x 32b bit tile -> coalesced float out.
__global__ void expand_kernel(float* __restrict__ out) {
    int tile = blockIdx.x * (blockDim.x >> 5) + (threadIdx.x >> 5);
    int lane = threadIdx.x & 31;
    if (tile >= (N_DIM / 32) * BW_DIM) return;
    int nn = tile >> 5;
    int bb = tile & 31;

    unsigned rw = outbitT[(nn * 32 + lane) * BW_DIM + bb];
    unsigned tx = warp_bit_transpose(rw, lane);
#pragma unroll
    for (int j = 0; j < 32; ++j) {
        unsigned wj = __shfl_sync(0xFFFFFFFFu, tx, j);
        out[(size_t)(bb * 32 + j) * N_DIM + nn * 32 + lane] = (float)((wj >> lane) & 1u);
    }
}

extern "C" void kernel_launch(void* const* d_in, const int* in_sizes, int n_in,
                              void* d_out, int out_size) {
    const int* input_bits  = nullptr;
    const int* connections = nullptr;
    const int* memory      = nullptr;

    for (int i = 0; i < n_in; ++i) {
        long long s = in_sizes[i];
        if (s == (long long)N_DIM * K_DIM)            connections = (const int*)d_in[i];
        else if (s == (long long)N_DIM * 65536LL)     memory      = (const int*)d_in[i];
        else                                          input_bits  = (const int*)d_in[i];
    }

    // 32B L2 fetch granularity (measured: gather DRAM traffic 248->88MB).
    cudaStreamCaptureStatus cap = cudaStreamCaptureStatusNone;
    cudaStreamIsCapturing((cudaStream_t)0, &cap);
    if (cap == cudaStreamCaptureStatusNone) {
        cudaDeviceSetLimit(cudaLimitMaxL2FetchGranularity, 32);
        cudaGetLastError();
    }

    pack_transpose_kernel<<<(BW_DIM * (T_DIM / 32) * 2) / 8, 256>>>(input_bits);
    ram_gather_kernel<<<N_DIM, GTHREADS>>>(connections, memory);
    expand_kernel<<<((N_DIM / 32) * BW_DIM) / 8, 256>>>((float*)d_out);
}

// round 16
// speedup vs baseline: 2.1596x; 1.0481x over previous
#include <cuda_runtime.h>
#include <cstdint>

// Problem constants (B=1024, T=4096, N=2048, K=16, M=2^16)
#define T_DIM   4096
#define N_DIM   2048
#define K_DIM   16
#define B_DIM   1024
#define BW_DIM  (B_DIM / 32)     // 32 b-words per bit-plane
#define GTHREADS 512

// Bit-plane transposed input, layout [bw][t]: tbit[bw*T + t], bit (b&31) = input[b][t].
__device__ unsigned tbit[BW_DIM * T_DIM];
// Bit-packed result: outbitT[n][w], bit (b&31) of word w = result(b, n). 256 KB.
__device__ unsigned outbitT[N_DIM * BW_DIM];

// 5-stage warp bit-matrix transpose (32x32).
__device__ __forceinline__ unsigned warp_bit_transpose(unsigned x, int lane) {
#pragma unroll
    for (int k = 16; k >= 1; k >>= 1) {
        unsigned mask = (k == 16) ? 0xFFFF0000u :
                        (k ==  8) ? 0xFF00FF00u :
                        (k ==  4) ? 0xF0F0F0F0u :
                        (k ==  2) ? 0xCCCCCCCCu : 0xAAAAAAAAu;
        unsigned y = __shfl_xor_sync(0xFFFFFFFFu, x, k);
        if ((lane & k) == 0) x = (x & ~mask) | ((y << k) &  mask);
        else                 x = (x &  mask) | ((y >> k) & ~mask);
    }
    return x;
}

// Pack v3: one warp per 16b x 32t HALF-tile.
__global__ void pack_transpose_kernel(const int* __restrict__ in) {
    int ht   = blockIdx.x * (blockDim.x >> 5) + (threadIdx.x >> 5);
    int lane = threadIdx.x & 31;
    if (ht >= BW_DIM * (T_DIM / 32) * 2) return;
    int half = ht & 1;
    int tile = ht >> 1;
    int bb = tile >> 7;
    int wt = tile & 127;
    int b0 = bb * 32 + half * 16;

    int v[16];
    const int* base = in + (size_t)b0 * T_DIM + wt * 32 + lane;
#pragma unroll
    for (int i = 0; i < 16; ++i) v[i] = base[(size_t)i * T_DIM];

    unsigned rw = 0;
#pragma unroll
    for (int i = 0; i < 16; ++i) {
        unsigned w = __ballot_sync(0xFFFFFFFFu, v[i] != 0);
        if (lane == i) rw = w;
    }
    unsigned tx = warp_bit_transpose(rw, lane);
    size_t word = (size_t)bb * T_DIM + wt * 32 + lane;
    ((unsigned short*)tbit)[word * 2 + half] = (unsigned short)(tx & 0xFFFFu);
}

__device__ __forceinline__ int ldcg_i32(const int* p) {
    int v;
    asm volatile("ld.global.cg.b32 %0, [%1];" : "=r"(v) : "l"(p));
    return v;
}

// One CTA per neuron. Counting sort with SINGLE atomic pass:
// atomicAdd's return value IS the within-bucket rank, so placement
// after the scan needs no atomics (pos = head[key] + rank).
__global__ __launch_bounds__(GTHREADS)
void ram_gather_kernel(const int* __restrict__ conn,     // [N, K]
                       const int* __restrict__ memory)   // [N, M]
{
    const int n    = blockIdx.x;
    const int tid  = threadIdx.x;
    const int lane = tid & 31;
    const int warp = tid >> 5;

    __shared__ unsigned cnt[256];
    __shared__ unsigned head[256];
    __shared__ unsigned wsum[8];
    __shared__ unsigned sorted[B_DIM];      // (b<<16) | addr
    __shared__ unsigned char res[B_DIM];

    if (tid < 256) cnt[tid] = 0;

    // Per-warp direct conn load (L1-hot 64B, no smem staging / no barrier).
    int myc = (lane < K_DIM) ? __ldg(&conn[n * K_DIM + lane]) : 0;
    __syncthreads();   // cnt zeroed

    // ---- Build addresses (one bit-transpose per 32 items) + histogram ----
    unsigned myA[B_DIM / GTHREADS];      // (b<<16) | addr
    unsigned myR[B_DIM / GTHREADS];      // rank within bucket
#pragma unroll
    for (int j = 0; j < B_DIM / GTHREADS; ++j) {
        int b  = j * GTHREADS + tid;
        int bw = b >> 5;                       // constant per warp
        unsigned w16 = 0;
        if (lane < K_DIM) w16 = __ldg(&tbit[(size_t)bw * T_DIM + myc]);
        unsigned a = warp_bit_transpose(w16, lane) & 0xFFFFu;
        myA[j] = ((unsigned)b << 16) | a;
        myR[j] = atomicAdd(&cnt[a >> 8], 1u);  // histogram + rank in one op
    }
    __syncthreads();

    // ---- Exclusive scan of 256 counts: warp-shuffle scan ----
    if (tid < 256) {
        unsigned v = cnt[tid];
        unsigned s = v;
#pragma unroll
        for (int d = 1; d < 32; d <<= 1) {
            unsigned t = __shfl_up_sync(0xFFFFFFFFu, s, d);
            if (lane >= d) s += t;
        }
        if (lane == 31) wsum[warp] = s;
        head[tid] = s - v;
    }
    __syncthreads();
    if (tid < 256) {
        unsigned off = 0;
#pragma unroll
        for (int w = 0; w < 8; ++w) off += (w < warp) ? wsum[w] : 0u;
        head[tid] += off;
    }
    __syncthreads();

    // ---- Place items (atomic-free: pos = head[key] + rank) ----
#pragma unroll
    for (int j = 0; j < B_DIM / GTHREADS; ++j) {
        unsigned key = (myA[j] & 0xFFFFu) >> 8;
        sorted[head[key] + myR[j]] = myA[j];
    }
    __syncthreads();

    // ---- Row-sorted gather; results staged as smem bytes ----
    const int* mrow = memory + ((size_t)n << 16);
    unsigned s0 = sorted[tid];
    unsigned s1 = sorted[GTHREADS + tid];
    int v0 = ldcg_i32(mrow + (s0 & 0xFFFFu));
    int v1 = ldcg_i32(mrow + (s1 & 0xFFFFu));
    res[s0 >> 16] = (unsigned char)(v0 & 1);
    res[s1 >> 16] = (unsigned char)(v1 & 1);
    __syncthreads();

    // ---- Bit-pack: 32 words, each warp handles 2 ----
    for (int w = warp; w < BW_DIM; w += GTHREADS / 32) {
        unsigned word = __ballot_sync(0xFFFFFFFFu, res[w * 32 + lane] != 0);
        if (lane == 0) outbitT[n * BW_DIM + w] = word;
    }
}

// Expand + transpose: one warp per 32n x 32b bit tile -> coalesced float out.
__global__ void expand_kernel(float* __restrict__ out) {
    int tile = blockIdx.x * (blockDim.x >> 5) + (threadIdx.x >> 5);
    int lane = threadIdx.x & 31;
    if (tile >= (N_DIM / 32) * BW_DIM) return;
    int nn = tile >> 5;
    int bb = tile & 31;

    unsigned rw = outbitT[(nn * 32 + lane) * BW_DIM + bb];
    unsigned tx = warp_bit_transpose(rw, lane);
#pragma unroll
    for (int j = 0; j < 32; ++j) {
        unsigned wj = __shfl_sync(0xFFFFFFFFu, tx, j);
        out[(size_t)(bb * 32 + j) * N_DIM + nn * 32 + lane] = (float)((wj >> lane) & 1u);
    }
}

extern "C" void kernel_launch(void* const* d_in, const int* in_sizes, int n_in,
                              void* d_out, int out_size) {
    const int* input_bits  = nullptr;
    const int* connections = nullptr;
    const int* memory      = nullptr;

    for (int i = 0; i < n_in; ++i) {
        long long s = in_sizes[i];
        if (s == (long long)N_DIM * K_DIM)            connections = (const int*)d_in[i];
        else if (s == (long long)N_DIM * 65536LL)     memory      = (const int*)d_in[i];
        else                                          input_bits  = (const int*)d_in[i];
    }

    // 32B L2 fetch granularity (measured: gather DRAM traffic 248->88MB).
    cudaStreamCaptureStatus cap = cudaStreamCaptureStatusNone;
    cudaStreamIsCapturing((cudaStream_t)0, &cap);
    if (cap == cudaStreamCaptureStatusNone) {
        cudaDeviceSetLimit(cudaLimitMaxL2FetchGranularity, 32);
        cudaGetLastError();
    }

    pack_transpose_kernel<<<(BW_DIM * (T_DIM / 32) * 2) / 8, 256>>>(input_bits);
    ram_gather_kernel<<<N_DIM, GTHREADS>>>(connections, memory);
    expand_kernel<<<((N_DIM / 32) * BW_DIM) / 8, 256>>>((float*)d_out);
}